// round 6
// baseline (speedup 1.0000x reference)
#include <cuda_runtime.h>

#define NPTS    8192
#define NCODES  16384
#define DIM     64

#define PB      32            // points per block
#define CT      512           // codes per tile
#define CHD     8             // d-rows per chunk
#define NCHUNK  ((NCODES / CT) * (DIM / CHD))   // 32 tiles * 8 phases = 256
#define RING    4

// output layout (floats)
#define OFF_ZQ     0
#define OFF_LOSS   524288
#define OFF_IDX    524289
#define OFF_NUNIQ  532481
#define OFF_USAGE  532482
#define OFF_TOTAL  548866

__device__ int    g_idx[NPTS];
__device__ float  g_b[NCODES];
__device__ float  g_eT[DIM * NCODES];   // transposed codebook [d][k]
__device__ double g_loss;

// ---------------------------------------------------------------------------
// packed f32x2 helpers
// ---------------------------------------------------------------------------
#define FMA2(acc, a, b) \
    asm("fma.rn.f32x2 %0, %1, %2, %0;" : "+l"(acc) : "l"(a), "l"(b))
#define UNPACK2(lo, hi, v) \
    asm("mov.b64 {%0, %1}, %2;" : "=f"(lo), "=f"(hi) : "l"(v))

__device__ __forceinline__ void cp_async16(void* smem_dst, const void* gmem_src) {
    unsigned s = (unsigned)__cvta_generic_to_shared(smem_dst);
    asm volatile("cp.async.cg.shared.global [%0], [%1], 16;" :: "r"(s), "l"(gmem_src));
}
__device__ __forceinline__ void cp_commit() {
    asm volatile("cp.async.commit_group;");
}
__device__ __forceinline__ void cp_wait2() {
    asm volatile("cp.async.wait_group 2;");
}

// ---------------------------------------------------------------------------
// 0) init
// ---------------------------------------------------------------------------
__global__ void vq_init(float* out) {
    int t = blockIdx.x * blockDim.x + threadIdx.x;
    if (t < NCODES) out[OFF_USAGE + t] = 0.0f;
    if (t == 0) g_loss = 0.0;
}

// ---------------------------------------------------------------------------
// 1) transpose codebook [k][d] -> g_eT [d][k]
// ---------------------------------------------------------------------------
__global__ void vq_transpose(const float* __restrict__ emb) {
    __shared__ float t[32][33];
    int kb = blockIdx.x * 32;
    int db = blockIdx.y * 32;
    int x = threadIdx.x, y = threadIdx.y;  // 32 x 8
    for (int yy = y; yy < 32; yy += 8)
        t[yy][x] = emb[(size_t)(kb + yy) * DIM + db + x];
    __syncthreads();
    for (int yy = y; yy < 32; yy += 8)
        g_eT[(size_t)(db + yy) * NCODES + kb + x] = t[x][yy];
}

// ---------------------------------------------------------------------------
// 2) b_k = sum_d e[k][d]^2
// ---------------------------------------------------------------------------
__global__ void vq_codenorm(const float* __restrict__ emb) {
    int k = blockIdx.x * blockDim.x + threadIdx.x;
    if (k >= NCODES) return;
    const float* row = emb + (size_t)k * DIM;
    float s = 0.0f;
#pragma unroll 8
    for (int d = 0; d < DIM; ++d) s = fmaf(row[d], row[d], s);
    g_b[k] = s;
}

// ---------------------------------------------------------------------------
// 3) main argmin kernel (fused zq/loss epilogue)
//    256 threads, 2 CTAs/SM. 32 points x 16384 codes.
//    4 point-groups (8 pts) x 64 code-lanes; thread tile 8 pts x 8 codes.
//    z is staged DUPLICATED (f32x2 dup pairs) so the inner loop has zero MOVs.
//    es: 4-deep ring of (8 d-rows x 512 codes) chunks, cp.async 3 ahead.
// ---------------------------------------------------------------------------
#define ES_FLOATS   (RING * CHD * CT)   // 16384
#define ZD_FLOATS   (DIM * 64)          // 4096 (dup pairs, stride 64)
#define OFF_ES      0
#define OFF_ZD      ES_FLOATS
#define OFF_SBB     (OFF_ZD + ZD_FLOATS)
#define OFF_SA      (OFF_SBB + 2 * CT)
#define SM_FLOATS   (OFF_SA + PB)       // 21536 floats = 86144 B

__device__ __forceinline__ void issue_chunk(float* es, float* sb, int idx, int tid) {
    const int slot = idx & (RING - 1);
    const int tile = idx >> 3;
    const int d0   = (idx & 7) * CHD;
#pragma unroll
    for (int i = 0; i < 4; ++i) {
        int u   = tid + i * 256;      // 1024 units of 16B
        int row = u >> 7;             // 0..7
        int col = (u & 127) * 4;      // float col 0..508
        cp_async16(es + slot * (CHD * CT) + row * CT + col,
                   g_eT + (size_t)(d0 + row) * NCODES + tile * CT + col);
    }
    if ((idx & 7) == 0 && tid < 128) {
        cp_async16(sb + (tile & 1) * CT + tid * 4, g_b + tile * CT + tid * 4);
    }
}

__global__ __launch_bounds__(256, 2)
void vq_argmin(const float* __restrict__ z, const float* __restrict__ emb,
               float* __restrict__ out) {
    extern __shared__ float smem[];
    float* es   = smem + OFF_ES;
    float* zdup = smem + OFF_ZD;
    float* sb   = smem + OFF_SBB;
    float* sa   = smem + OFF_SA;

    const int tid = threadIdx.x;
    const int grp = tid >> 6;          // 0..3 : points grp*8..+7
    const int l64 = tid & 63;          // codes 4*l64 and 4*l64+256 within tile

    const int pbase   = blockIdx.x * PB;
    const int bb      = pbase >> 10;
    const int posbase = pbase & 1023;

    // prologue: 3 chunks in flight
    issue_chunk(es, sb, 0, tid); cp_commit();
    issue_chunk(es, sb, 1, tid); cp_commit();
    issue_chunk(es, sb, 2, tid); cp_commit();

    // stage z duplicated: zdup[d][2*pos] = zdup[d][2*pos+1] = z
    for (int t = tid; t < DIM * PB; t += 256) {
        int d = t >> 5, pos = t & 31;
        float v = z[(size_t)bb * 65536 + (size_t)d * 1024 + posbase + pos];
        *(float2*)(zdup + d * 64 + pos * 2) = make_float2(v, v);
    }
    __syncthreads();

    // a_p = sum_d fl(z^2), strictly sequential d (match jnp.sum order)
    if (tid < PB) {
        float s = 0.0f;
        for (int d = 0; d < DIM; ++d) {
            float v = zdup[d * 64 + tid * 2];
            s = __fadd_rn(s, __fmul_rn(v, v));
        }
        sa[tid] = s;
    }
    __syncthreads();

    float a_r[8];
#pragma unroll
    for (int i = 0; i < 8; ++i) a_r[i] = sa[grp * 8 + i];

    float bestd[8];
    int   bestk[8];
#pragma unroll
    for (int i = 0; i < 8; ++i) { bestd[i] = __int_as_float(0x7f800000); bestk[i] = 0; }

    unsigned long long acc[8][4];
#pragma unroll
    for (int i = 0; i < 8; ++i)
#pragma unroll
        for (int j = 0; j < 4; ++j) acc[i][j] = 0ULL;

    const float* zbase = zdup + grp * 16;   // 8 dup-pairs for this group

    for (int c = 0; c < NCHUNK; ++c) {
        cp_wait2();            // chunk c's group retired
        __syncthreads();       // chunk c visible; everyone done with c-1
        if (c + 3 < NCHUNK) issue_chunk(es, sb, c + 3, tid);
        cp_commit();           // always commit (possibly empty group)

        const float* ebase = es + (c & (RING - 1)) * (CHD * CT) + l64 * 4;
        const int d0 = (c & 7) * CHD;

#pragma unroll
        for (int dd = 0; dd < CHD; ++dd) {
            // z: 8 dup-pairs via 4 broadcast LDS.128 (zero MOVs)
            const ulonglong2* zp =
                (const ulonglong2*)(zbase + (d0 + dd) * 64);
            const ulonglong2 z01 = zp[0];
            const ulonglong2 z23 = zp[1];
            const ulonglong2 z45 = zp[2];
            const ulonglong2 z67 = zp[3];

            // e: 8 codes = 4 packed pairs via 2 LDS.128
            const float* erow = ebase + dd * CT;
            const ulonglong2 eA = *(const ulonglong2*)(erow);
            const ulonglong2 eB = *(const ulonglong2*)(erow + 256);

            FMA2(acc[0][0], z01.x, eA.x); FMA2(acc[0][1], z01.x, eA.y);
            FMA2(acc[0][2], z01.x, eB.x); FMA2(acc[0][3], z01.x, eB.y);
            FMA2(acc[1][0], z01.y, eA.x); FMA2(acc[1][1], z01.y, eA.y);
            FMA2(acc[1][2], z01.y, eB.x); FMA2(acc[1][3], z01.y, eB.y);
            FMA2(acc[2][0], z23.x, eA.x); FMA2(acc[2][1], z23.x, eA.y);
            FMA2(acc[2][2], z23.x, eB.x); FMA2(acc[2][3], z23.x, eB.y);
            FMA2(acc[3][0], z23.y, eA.x); FMA2(acc[3][1], z23.y, eA.y);
            FMA2(acc[3][2], z23.y, eB.x); FMA2(acc[3][3], z23.y, eB.y);
            FMA2(acc[4][0], z45.x, eA.x); FMA2(acc[4][1], z45.x, eA.y);
            FMA2(acc[4][2], z45.x, eB.x); FMA2(acc[4][3], z45.x, eB.y);
            FMA2(acc[5][0], z45.y, eA.x); FMA2(acc[5][1], z45.y, eA.y);
            FMA2(acc[5][2], z45.y, eB.x); FMA2(acc[5][3], z45.y, eB.y);
            FMA2(acc[6][0], z67.x, eA.x); FMA2(acc[6][1], z67.x, eA.y);
            FMA2(acc[6][2], z67.x, eB.x); FMA2(acc[6][3], z67.x, eB.y);
            FMA2(acc[7][0], z67.y, eA.x); FMA2(acc[7][1], z67.y, eA.y);
            FMA2(acc[7][2], z67.y, eB.x); FMA2(acc[7][3], z67.y, eB.y);
        }

        if ((c & 7) == 7) {
            // tile epilogue: dist = fl( fl(a+b) - 2c ), ascending k in-thread
            const int tile  = c >> 3;
            const int kbase = tile * CT;
            const float* sbc = sb + (tile & 1) * CT + l64 * 4;
            const float4 bA = *(const float4*)(sbc);
            const float4 bB = *(const float4*)(sbc + 256);
            const int kA = kbase + l64 * 4;
            const int kB = kA + 256;
#pragma unroll
            for (int i = 0; i < 8; ++i) {
                float c0, c1, c2, c3;
                UNPACK2(c0, c1, acc[i][0]);
                UNPACK2(c2, c3, acc[i][1]);
                float d0v = fmaf(-2.0f, c0, __fadd_rn(a_r[i], bA.x));
                float d1v = fmaf(-2.0f, c1, __fadd_rn(a_r[i], bA.y));
                float d2v = fmaf(-2.0f, c2, __fadd_rn(a_r[i], bA.z));
                float d3v = fmaf(-2.0f, c3, __fadd_rn(a_r[i], bA.w));
                if (d0v < bestd[i]) { bestd[i] = d0v; bestk[i] = kA;     }
                if (d1v < bestd[i]) { bestd[i] = d1v; bestk[i] = kA + 1; }
                if (d2v < bestd[i]) { bestd[i] = d2v; bestk[i] = kA + 2; }
                if (d3v < bestd[i]) { bestd[i] = d3v; bestk[i] = kA + 3; }
                UNPACK2(c0, c1, acc[i][2]);
                UNPACK2(c2, c3, acc[i][3]);
                d0v = fmaf(-2.0f, c0, __fadd_rn(a_r[i], bB.x));
                d1v = fmaf(-2.0f, c1, __fadd_rn(a_r[i], bB.y));
                d2v = fmaf(-2.0f, c2, __fadd_rn(a_r[i], bB.z));
                d3v = fmaf(-2.0f, c3, __fadd_rn(a_r[i], bB.w));
                if (d0v < bestd[i]) { bestd[i] = d0v; bestk[i] = kB;     }
                if (d1v < bestd[i]) { bestd[i] = d1v; bestk[i] = kB + 1; }
                if (d2v < bestd[i]) { bestd[i] = d2v; bestk[i] = kB + 2; }
                if (d3v < bestd[i]) { bestd[i] = d3v; bestk[i] = kB + 3; }
                acc[i][0] = 0ULL; acc[i][1] = 0ULL;
                acc[i][2] = 0ULL; acc[i][3] = 0ULL;
            }
        }
    }

    // cross-thread reduction with (d, k) lexicographic min (es region reused)
    __syncthreads();
    float* rd = smem;                       // [0,   2048)
    int*   ri = (int*)(smem + 2048);        // [2048,4096)
    int*   ki = (int*)(smem + 4096);        // [4096,4128)
    double* ld = (double*)(smem + 4352);    // [4352,4864) 256 doubles
#pragma unroll
    for (int i = 0; i < 8; ++i) {
        rd[tid * 8 + i] = bestd[i];
        ri[tid * 8 + i] = bestk[i];
    }
    __syncthreads();

    if (tid < PB) {
        int p  = tid;
        int mg = p >> 3;
        int mi = p & 7;
        float bd = __int_as_float(0x7f800000);
        int   bk = 0x7fffffff;
        for (int t = 0; t < 64; ++t) {
            int   t2 = (mg * 64 + t) * 8 + mi;
            float dd = rd[t2];
            int   kk = ri[t2];
            if (dd < bd || (dd == bd && kk < bk)) { bd = dd; bk = kk; }
        }
        ki[p] = bk;
        g_idx[pbase + p] = bk;
        out[OFF_IDX + pbase + p] = (float)bk;
        out[OFF_USAGE + bk] = 1.0f;          // idempotent scatter
    }
    __syncthreads();

    // fused z_q gather + loss: thread owns point p = tid&31, d = (tid>>5)+8i
    {
        const int p = tid & 31;
        const int k = ki[p];
        const float* erow = emb + (size_t)k * DIM;
        double lacc = 0.0;
#pragma unroll
        for (int i = 0; i < 8; ++i) {
            int d = (tid >> 5) + i * 8;
            float e  = erow[d];
            float zv = zdup[d * 64 + p * 2];
            out[OFF_ZQ + (size_t)bb * 65536 + (size_t)d * 1024 + posbase + p] = e;
            float diff = e - zv;
            lacc += (double)diff * (double)diff;
        }
        ld[tid] = lacc;
    }
    __syncthreads();
    for (int s = 128; s > 0; s >>= 1) {
        if (tid < s) ld[tid] += ld[tid + s];
        __syncthreads();
    }
    if (tid == 0) atomicAdd(&g_loss, ld[0]);
}

// ---------------------------------------------------------------------------
// 4) finalize
// ---------------------------------------------------------------------------
__global__ void vq_finalize(float* out) {
    __shared__ float sf[512];
    float s = 0.0f;
    for (int t = threadIdx.x; t < NCODES; t += 512) s += out[OFF_USAGE + t];
    sf[threadIdx.x] = s;
    __syncthreads();
    for (int st = 256; st > 0; st >>= 1) {
        if (threadIdx.x < st) sf[threadIdx.x] += sf[threadIdx.x + st];
        __syncthreads();
    }
    if (threadIdx.x == 0) {
        float total = sf[0];
        out[OFF_NUNIQ] = total;
        out[OFF_TOTAL] = total / (float)NCODES;
        float m = (float)(g_loss / 524288.0);
        out[OFF_LOSS] = m + 0.25f * m;
    }
}

// ---------------------------------------------------------------------------
extern "C" void kernel_launch(void* const* d_in, const int* in_sizes, int n_in,
                              void* d_out, int out_size) {
    const float* z;
    const float* emb;
    if (in_sizes[0] == 524288) {
        z = (const float*)d_in[0];
        emb = (const float*)d_in[1];
    } else {
        z = (const float*)d_in[1];
        emb = (const float*)d_in[0];
    }
    float* out = (float*)d_out;

    static int attr_set = 0;
    if (!attr_set) {
        cudaFuncSetAttribute(vq_argmin, cudaFuncAttributeMaxDynamicSharedMemorySize,
                             SM_FLOATS * (int)sizeof(float));
        attr_set = 1;
    }

    vq_init<<<(NCODES + 255) / 256, 256>>>(out);
    vq_transpose<<<dim3(NCODES / 32, DIM / 32), dim3(32, 8)>>>(emb);
    vq_codenorm<<<(NCODES + 255) / 256, 256>>>(emb);
    vq_argmin<<<NPTS / PB, 256, SM_FLOATS * sizeof(float)>>>(z, emb, out);
    vq_finalize<<<1, 512>>>(out);
}

// round 7
// speedup vs baseline: 1.1618x; 1.1618x over previous
#include <cuda_runtime.h>

#define NPTS    8192
#define NCODES  16384
#define DIM     64

#define PB      32            // points per block
#define CT      512           // codes per tile
#define CHD     8             // d-rows per chunk
#define NCHUNK  ((NCODES / CT) * (DIM / CHD))   // 32 tiles * 8 phases = 256
#define RING    4

// output layout (floats)
#define OFF_ZQ     0
#define OFF_LOSS   524288
#define OFF_IDX    524289
#define OFF_NUNIQ  532481
#define OFF_USAGE  532482
#define OFF_TOTAL  548866

__device__ int    g_idx[NPTS];
__device__ float  g_b[NCODES];
__device__ float  g_eT[DIM * NCODES];   // transposed codebook [d][k]
__device__ double g_loss;

// ---------------------------------------------------------------------------
// packed f32x2 helpers
// ---------------------------------------------------------------------------
#define PACK_DUP(dst, f) \
    asm("mov.b64 %0, {%1, %1};" : "=l"(dst) : "f"(f))
#define FMA2(acc, a, b) \
    asm("fma.rn.f32x2 %0, %1, %2, %0;" : "+l"(acc) : "l"(a), "l"(b))
#define UNPACK2(lo, hi, v) \
    asm("mov.b64 {%0, %1}, %2;" : "=f"(lo), "=f"(hi) : "l"(v))

__device__ __forceinline__ void cp_async16(void* smem_dst, const void* gmem_src) {
    unsigned s = (unsigned)__cvta_generic_to_shared(smem_dst);
    asm volatile("cp.async.cg.shared.global [%0], [%1], 16;" :: "r"(s), "l"(gmem_src));
}
__device__ __forceinline__ void cp_commit() {
    asm volatile("cp.async.commit_group;");
}
__device__ __forceinline__ void cp_wait2() {
    asm volatile("cp.async.wait_group 2;");
}

// ---------------------------------------------------------------------------
// 0) transpose codebook [k][d] -> g_eT [d][k]
// ---------------------------------------------------------------------------
__global__ void vq_transpose(const float* __restrict__ emb) {
    __shared__ float t[32][33];
    int kb = blockIdx.x * 32;
    int db = blockIdx.y * 32;
    int x = threadIdx.x, y = threadIdx.y;  // 32 x 8
    for (int yy = y; yy < 32; yy += 8)
        t[yy][x] = emb[(size_t)(kb + yy) * DIM + db + x];
    __syncthreads();
    for (int yy = y; yy < 32; yy += 8)
        g_eT[(size_t)(db + yy) * NCODES + kb + x] = t[x][yy];
}

// ---------------------------------------------------------------------------
// 1) fused: b_k = sum_d e[k][d]^2 ; zero usage ; zero loss
// ---------------------------------------------------------------------------
__global__ void vq_codenorm_init(const float* __restrict__ emb, float* out) {
    int k = blockIdx.x * blockDim.x + threadIdx.x;
    if (k >= NCODES) return;
    const float* row = emb + (size_t)k * DIM;
    float s = 0.0f;
#pragma unroll 8
    for (int d = 0; d < DIM; ++d) s = fmaf(row[d], row[d], s);
    g_b[k] = s;
    out[OFF_USAGE + k] = 0.0f;
    if (k == 0) g_loss = 0.0;
}

// ---------------------------------------------------------------------------
// 2) main argmin kernel (R4 mainloop + fused zq/loss epilogue)
//    256 threads, 2 CTAs/SM. 32 points x 16384 codes.
//    4 point-groups (8 pts) x 64 code-lanes; thread tile 8 pts x 8 codes.
//    es: 4-deep ring of (8 d-rows x 512 codes) chunks, cp.async 3 ahead.
// ---------------------------------------------------------------------------
#define ES_FLOATS   (RING * CHD * CT)   // 16384
#define ZS_STRIDE   36
#define ZS_FLOATS   (DIM * ZS_STRIDE)   // 2304
#define OFF_ES      0
#define OFF_ZS      ES_FLOATS
#define OFF_SBB     (OFF_ZS + ZS_FLOATS)
#define OFF_SA      (OFF_SBB + 2 * CT)
#define SM_FLOATS   (OFF_SA + PB)       // 19744 floats = 78976 B

__device__ __forceinline__ void issue_chunk(float* es, float* sb, int idx, int tid) {
    const int slot = idx & (RING - 1);
    const int tile = idx >> 3;
    const int d0   = (idx & 7) * CHD;
#pragma unroll
    for (int i = 0; i < 4; ++i) {
        int u   = tid + i * 256;      // 1024 units of 16B
        int row = u >> 7;             // 0..7
        int col = (u & 127) * 4;      // float col 0..508
        cp_async16(es + slot * (CHD * CT) + row * CT + col,
                   g_eT + (size_t)(d0 + row) * NCODES + tile * CT + col);
    }
    if ((idx & 7) == 0 && tid < 128) {
        cp_async16(sb + (tile & 1) * CT + tid * 4, g_b + tile * CT + tid * 4);
    }
}

__global__ __launch_bounds__(256, 2)
void vq_argmin(const float* __restrict__ z, const float* __restrict__ emb,
               float* __restrict__ out) {
    extern __shared__ float smem[];
    float* es = smem + OFF_ES;
    float* zs = smem + OFF_ZS;
    float* sb = smem + OFF_SBB;
    float* sa = smem + OFF_SA;

    const int tid = threadIdx.x;
    const int grp = tid >> 6;          // 0..3 : points grp*8..+7
    const int l64 = tid & 63;          // codes 4*l64 and 4*l64+256 within tile

    const int pbase   = blockIdx.x * PB;
    const int bb      = pbase >> 10;
    const int posbase = pbase & 1023;

    // prologue: 3 chunks in flight
    issue_chunk(es, sb, 0, tid); cp_commit();
    issue_chunk(es, sb, 1, tid); cp_commit();
    issue_chunk(es, sb, 2, tid); cp_commit();

    // stage z: zs[d][pos], pos < 32
    for (int t = tid; t < DIM * PB; t += 256) {
        int d = t >> 5, pos = t & 31;
        zs[d * ZS_STRIDE + pos] =
            z[(size_t)bb * 65536 + (size_t)d * 1024 + posbase + pos];
    }
    __syncthreads();

    // a_p = sum_d fl(z^2), strictly sequential d (match jnp.sum order)
    if (tid < PB) {
        float s = 0.0f;
        for (int d = 0; d < DIM; ++d) {
            float v = zs[d * ZS_STRIDE + tid];
            s = __fadd_rn(s, __fmul_rn(v, v));
        }
        sa[tid] = s;
    }
    __syncthreads();

    float a_r[8];
#pragma unroll
    for (int i = 0; i < 8; ++i) a_r[i] = sa[grp * 8 + i];

    float bestd[8];
    int   bestk[8];
#pragma unroll
    for (int i = 0; i < 8; ++i) { bestd[i] = __int_as_float(0x7f800000); bestk[i] = 0; }

    unsigned long long acc[8][4];
#pragma unroll
    for (int i = 0; i < 8; ++i)
#pragma unroll
        for (int j = 0; j < 4; ++j) acc[i][j] = 0ULL;

    const float* zbase = zs + grp * 8;

    for (int c = 0; c < NCHUNK; ++c) {
        cp_wait2();            // chunk c's group retired
        __syncthreads();       // chunk c visible to all; all done with c-1
        if (c + 3 < NCHUNK) issue_chunk(es, sb, c + 3, tid);
        cp_commit();           // always commit (possibly empty group)

        const float* ebase = es + (c & (RING - 1)) * (CHD * CT) + l64 * 4;
        const int d0 = (c & 7) * CHD;

#pragma unroll 4
        for (int dd = 0; dd < CHD; ++dd) {
            const float* zrow = zbase + (d0 + dd) * ZS_STRIDE;
            const float4 za = *(const float4*)(zrow);
            const float4 zb = *(const float4*)(zrow + 4);
            unsigned long long zz[8];
            PACK_DUP(zz[0], za.x); PACK_DUP(zz[1], za.y);
            PACK_DUP(zz[2], za.z); PACK_DUP(zz[3], za.w);
            PACK_DUP(zz[4], zb.x); PACK_DUP(zz[5], zb.y);
            PACK_DUP(zz[6], zb.z); PACK_DUP(zz[7], zb.w);

            const float* erow = ebase + dd * CT;
            const ulonglong2 eA = *(const ulonglong2*)(erow);
            const ulonglong2 eB = *(const ulonglong2*)(erow + 256);

#pragma unroll
            for (int i = 0; i < 8; ++i) {
                FMA2(acc[i][0], zz[i], eA.x);
                FMA2(acc[i][1], zz[i], eA.y);
                FMA2(acc[i][2], zz[i], eB.x);
                FMA2(acc[i][3], zz[i], eB.y);
            }
        }

        if ((c & 7) == 7) {
            // tile epilogue: dist = fl( fl(a+b) - 2c ), ascending k in-thread
            const int tile  = c >> 3;
            const int kbase = tile * CT;
            const float* sbc = sb + (tile & 1) * CT + l64 * 4;
            const float4 bA = *(const float4*)(sbc);
            const float4 bB = *(const float4*)(sbc + 256);
            const int kA = kbase + l64 * 4;
            const int kB = kA + 256;
#pragma unroll
            for (int i = 0; i < 8; ++i) {
                float c0, c1, c2, c3;
                UNPACK2(c0, c1, acc[i][0]);
                UNPACK2(c2, c3, acc[i][1]);
                float d0v = fmaf(-2.0f, c0, __fadd_rn(a_r[i], bA.x));
                float d1v = fmaf(-2.0f, c1, __fadd_rn(a_r[i], bA.y));
                float d2v = fmaf(-2.0f, c2, __fadd_rn(a_r[i], bA.z));
                float d3v = fmaf(-2.0f, c3, __fadd_rn(a_r[i], bA.w));
                if (d0v < bestd[i]) { bestd[i] = d0v; bestk[i] = kA;     }
                if (d1v < bestd[i]) { bestd[i] = d1v; bestk[i] = kA + 1; }
                if (d2v < bestd[i]) { bestd[i] = d2v; bestk[i] = kA + 2; }
                if (d3v < bestd[i]) { bestd[i] = d3v; bestk[i] = kA + 3; }
                UNPACK2(c0, c1, acc[i][2]);
                UNPACK2(c2, c3, acc[i][3]);
                d0v = fmaf(-2.0f, c0, __fadd_rn(a_r[i], bB.x));
                d1v = fmaf(-2.0f, c1, __fadd_rn(a_r[i], bB.y));
                d2v = fmaf(-2.0f, c2, __fadd_rn(a_r[i], bB.z));
                d3v = fmaf(-2.0f, c3, __fadd_rn(a_r[i], bB.w));
                if (d0v < bestd[i]) { bestd[i] = d0v; bestk[i] = kB;     }
                if (d1v < bestd[i]) { bestd[i] = d1v; bestk[i] = kB + 1; }
                if (d2v < bestd[i]) { bestd[i] = d2v; bestk[i] = kB + 2; }
                if (d3v < bestd[i]) { bestd[i] = d3v; bestk[i] = kB + 3; }
                acc[i][0] = 0ULL; acc[i][1] = 0ULL;
                acc[i][2] = 0ULL; acc[i][3] = 0ULL;
            }
        }
    }

    // cross-thread reduction with (d, k) lexicographic min (es region reused)
    __syncthreads();
    float* rd = smem;                       // [0,   2048)
    int*   ri = (int*)(smem + 2048);        // [2048,4096)
    int*   ki = (int*)(smem + 4096);        // [4096,4128)
    double* ld = (double*)(smem + 4352);    // [4352,4864) 256 doubles
#pragma unroll
    for (int i = 0; i < 8; ++i) {
        rd[tid * 8 + i] = bestd[i];
        ri[tid * 8 + i] = bestk[i];
    }
    __syncthreads();

    if (tid < PB) {
        int p  = tid;
        int mg = p >> 3;
        int mi = p & 7;
        float bd = __int_as_float(0x7f800000);
        int   bk = 0x7fffffff;
        for (int t = 0; t < 64; ++t) {
            int   t2 = (mg * 64 + t) * 8 + mi;
            float dd = rd[t2];
            int   kk = ri[t2];
            if (dd < bd || (dd == bd && kk < bk)) { bd = dd; bk = kk; }
        }
        ki[p] = bk;
        g_idx[pbase + p] = bk;
        out[OFF_IDX + pbase + p] = (float)bk;
        out[OFF_USAGE + bk] = 1.0f;          // idempotent scatter
    }
    __syncthreads();

    // fused z_q gather + loss: thread owns point p = tid&31, d = (tid>>5)+8i
    {
        const int p = tid & 31;
        const int k = ki[p];
        const float* erow = emb + (size_t)k * DIM;
        double lacc = 0.0;
#pragma unroll
        for (int i = 0; i < 8; ++i) {
            int d = (tid >> 5) + i * 8;
            float e  = erow[d];
            float zv = zs[d * ZS_STRIDE + p];
            out[OFF_ZQ + (size_t)bb * 65536 + (size_t)d * 1024 + posbase + p] = e;
            float diff = e - zv;
            lacc += (double)diff * (double)diff;
        }
        ld[tid] = lacc;
    }
    __syncthreads();
    for (int s = 128; s > 0; s >>= 1) {
        if (tid < s) ld[tid] += ld[tid + s];
        __syncthreads();
    }
    if (tid == 0) atomicAdd(&g_loss, ld[0]);
}

// ---------------------------------------------------------------------------
// 3) finalize
// ---------------------------------------------------------------------------
__global__ void vq_finalize(float* out) {
    __shared__ float sf[512];
    float s = 0.0f;
    for (int t = threadIdx.x; t < NCODES; t += 512) s += out[OFF_USAGE + t];
    sf[threadIdx.x] = s;
    __syncthreads();
    for (int st = 256; st > 0; st >>= 1) {
        if (threadIdx.x < st) sf[threadIdx.x] += sf[threadIdx.x + st];
        __syncthreads();
    }
    if (threadIdx.x == 0) {
        float total = sf[0];
        out[OFF_NUNIQ] = total;
        out[OFF_TOTAL] = total / (float)NCODES;
        float m = (float)(g_loss / 524288.0);
        out[OFF_LOSS] = m + 0.25f * m;
    }
}

// ---------------------------------------------------------------------------
extern "C" void kernel_launch(void* const* d_in, const int* in_sizes, int n_in,
                              void* d_out, int out_size) {
    const float* z;
    const float* emb;
    if (in_sizes[0] == 524288) {
        z = (const float*)d_in[0];
        emb = (const float*)d_in[1];
    } else {
        z = (const float*)d_in[1];
        emb = (const float*)d_in[0];
    }
    float* out = (float*)d_out;

    static int attr_set = 0;
    if (!attr_set) {
        cudaFuncSetAttribute(vq_argmin, cudaFuncAttributeMaxDynamicSharedMemorySize,
                             SM_FLOATS * (int)sizeof(float));
        attr_set = 1;
    }

    vq_transpose<<<dim3(NCODES / 32, DIM / 32), dim3(32, 8)>>>(emb);
    vq_codenorm_init<<<(NCODES + 255) / 256, 256>>>(emb, out);
    vq_argmin<<<NPTS / PB, 256, SM_FLOATS * sizeof(float)>>>(z, emb, out);
    vq_finalize<<<1, 512>>>(out);
}

// round 9
// speedup vs baseline: 2.3433x; 2.0169x over previous
#include <cuda_runtime.h>
#include <cuda_fp16.h>
#include <cstdint>

#define NPTS     8192
#define NCODES   16384
#define DIM      64
#define NBLK     256          // blocks of 64 codes
#define MARGIN   1.0f         // key-unit margin (error budget ~0.15)

// output layout (floats)
#define OFF_ZQ     0
#define OFF_LOSS   524288
#define OFF_IDX    524289
#define OFF_NUNIQ  532481
#define OFF_USAGE  532482
#define OFF_TOTAL  548866

__device__ int    g_idx[NPTS];
__device__ float  g_b[NCODES];
__device__ float  g_an[NPTS];
__device__ __half g_zh[NPTS * DIM];              // permuted fp16 z rows
__device__ __half g_eh[NCODES * DIM];            // permuted fp16 (-16384*e) rows
__device__ float  g_bmin[(size_t)NBLK * NPTS];   // 8 MB blockmins [block][point]
__device__ double g_loss;

// ---------------------------------------------------------------------------
// helpers
// ---------------------------------------------------------------------------
__device__ __forceinline__ unsigned smem_u32(const void* p) {
    unsigned a;
    asm("{ .reg .u64 t; cvta.to.shared.u64 t, %1; cvt.u32.u64 %0, t; }"
        : "=r"(a) : "l"(p));
    return a;
}
__device__ __forceinline__ void cp_async16(unsigned dst, const void* src) {
    asm volatile("cp.async.cg.shared.global [%0], [%1], 16;" :: "r"(dst), "l"(src));
}
#define CP_COMMIT() asm volatile("cp.async.commit_group;")
#define CP_WAIT1()  asm volatile("cp.async.wait_group 1;")

__device__ __forceinline__ void mma16816(float& d0, float& d1, float& d2, float& d3,
                                         unsigned a0, unsigned a1, unsigned a2, unsigned a3,
                                         unsigned b0, unsigned b1) {
    asm("mma.sync.aligned.m16n8k16.row.col.f32.f16.f16.f32 "
        "{%0,%1,%2,%3},{%4,%5,%6,%7},{%8,%9},{%0,%1,%2,%3};"
        : "+f"(d0), "+f"(d1), "+f"(d2), "+f"(d3)
        : "r"(a0), "r"(a1), "r"(a2), "r"(a3), "r"(b0), "r"(b1));
}

// fragment permutation: half index h (0..63) -> dim d
// h = t*16 + s*4 + j : d = 16s + 2t + (j<2 ? j : 6+j)
__device__ __forceinline__ int perm_d(int h) {
    int t = h >> 4, s = (h >> 2) & 3, j = h & 3;
    return 16 * s + 2 * t + (j < 2 ? j : 6 + j);
}

// ---------------------------------------------------------------------------
// P1: z prep — permuted fp16 rows + exact sequential-d norm
// ---------------------------------------------------------------------------
__global__ void vq_prep_z(const float* __restrict__ z) {
    int p = blockIdx.x * 128 + threadIdx.x;
    int b = p >> 10, pos = p & 1023;
    const float* zc = z + (size_t)b * 65536 + pos;
    float s = 0.0f;
    for (int d = 0; d < DIM; ++d) {
        float v = zc[(size_t)d * 1024];
        s = __fadd_rn(s, __fmul_rn(v, v));
    }
    g_an[p] = s;
    __half arr[64];
#pragma unroll
    for (int h = 0; h < 64; ++h)
        arr[h] = __float2half(zc[(size_t)perm_d(h) * 1024]);
    uint4* dst = (uint4*)(g_zh + (size_t)p * 64);
#pragma unroll
    for (int i = 0; i < 8; ++i) dst[i] = ((uint4*)arr)[i];
}

// ---------------------------------------------------------------------------
// P2: e prep — permuted fp16(-16384*e) rows, b_k, zero usage/loss
// ---------------------------------------------------------------------------
__global__ void vq_prep_e(const float* __restrict__ emb, float* out) {
    int k = blockIdx.x * 128 + threadIdx.x;
    const float* row = emb + (size_t)k * DIM;
    float ev[64];
    float s = 0.0f;
#pragma unroll 8
    for (int d = 0; d < DIM; ++d) {
        float e = row[d];
        ev[d] = e;
        s = fmaf(e, e, s);
    }
    g_b[k] = s;
    __half arr[64];
#pragma unroll
    for (int h = 0; h < 64; ++h)
        arr[h] = __float2half(ev[perm_d(h)] * -16384.0f);
    uint4* dst = (uint4*)(g_eh + (size_t)k * 64);
#pragma unroll
    for (int i = 0; i < 8; ++i) dst[i] = ((uint4*)arr)[i];
    out[OFF_USAGE + k] = 0.0f;
    if (k == 0) g_loss = 0.0;
}

// ---------------------------------------------------------------------------
// K1: HMMA prune — 128 CTAs x 128 thr (4 warps); warp = 16 pts x 16384 codes.
//     B tiles: 256 codes x 144B padded smem rows, 3-slot ring, cp.async.
//     Output: g_bmin[block][point] f32 (block = 64 codes).
// ---------------------------------------------------------------------------
#define TCO     256                      // codes per tile
#define ROWB    144                      // padded smem row bytes
#define SLOTB   (TCO * ROWB)             // 36864
#define SMK1    (3 * SLOTB)              // 110592

__device__ __forceinline__ void k1_load_tile(unsigned sb, int tile, int tid) {
    const char* src = (const char*)g_eh + (size_t)tile * TCO * 128;
#pragma unroll
    for (int i = 0; i < 16; ++i) {
        int u = tid + i * 128;           // 2048 granules
        int r = u >> 3, gr = u & 7;
        cp_async16(sb + r * ROWB + gr * 16, src + r * 128 + gr * 16);
    }
}

__global__ __launch_bounds__(128, 1)
void vq_hmma() {
    extern __shared__ char smem[];
    const unsigned sbase = smem_u32(smem);
    const int tid  = threadIdx.x;
    const int w    = tid >> 5;
    const int lane = tid & 31;
    const int g    = lane >> 2;
    const int t    = lane & 3;
    const int pb   = blockIdx.x * 64 + w * 16;   // warp's 16 points

    // prologue: tiles 0,1 in flight
    k1_load_tile(sbase + 0 * SLOTB, 0, tid); CP_COMMIT();
    k1_load_tile(sbase + 1 * SLOTB, 1, tid); CP_COMMIT();

    // A fragments (persist whole kernel)
    const uint4* za = (const uint4*)(g_zh + (size_t)(pb + g) * 64);
    const uint4* zb = (const uint4*)(g_zh + (size_t)(pb + g + 8) * 64);
    const uint4 rg0 = za[2 * t], rg1 = za[2 * t + 1];
    const uint4 rh0 = zb[2 * t], rh1 = zb[2 * t + 1];
    unsigned A[4][4] = {
        { rg0.x, rh0.x, rg0.y, rh0.y },
        { rg0.z, rh0.z, rg0.w, rh0.w },
        { rg1.x, rh1.x, rg1.y, rh1.y },
        { rg1.z, rh1.z, rg1.w, rh1.w } };

    const float INF = __int_as_float(0x7f800000);
    float mlo = INF, mhi = INF;

    for (int tile = 0; tile < 64; ++tile) {
        CP_WAIT1();
        __syncthreads();                    // tile resident; prev slot free
        if (tile + 2 < 64) k1_load_tile(sbase + ((tile + 2) % 3) * SLOTB, tile + 2, tid);
        CP_COMMIT();

        const unsigned bs = sbase + (tile % 3) * SLOTB;

#pragma unroll 2
        for (int nq = 0; nq < 8; ++nq) {    // 4 n8-tiles per group
            uint4 B0[4], B1[4];
#pragma unroll
            for (int j = 0; j < 4; ++j) {
                unsigned addr = bs + ((nq * 4 + j) * 8 + g) * ROWB + t * 32;
                asm("ld.shared.v4.u32 {%0,%1,%2,%3}, [%4];"
                    : "=r"(B0[j].x), "=r"(B0[j].y), "=r"(B0[j].z), "=r"(B0[j].w)
                    : "r"(addr));
                asm("ld.shared.v4.u32 {%0,%1,%2,%3}, [%4];"
                    : "=r"(B1[j].x), "=r"(B1[j].y), "=r"(B1[j].z), "=r"(B1[j].w)
                    : "r"(addr + 16));
            }
            float D[4][4];
#pragma unroll
            for (int j = 0; j < 4; ++j)
                D[j][0] = D[j][1] = D[j][2] = D[j][3] = 0.0f;
#pragma unroll
            for (int j = 0; j < 4; ++j) {
                mma16816(D[j][0], D[j][1], D[j][2], D[j][3],
                         A[0][0], A[0][1], A[0][2], A[0][3], B0[j].x, B0[j].y);
                mma16816(D[j][0], D[j][1], D[j][2], D[j][3],
                         A[1][0], A[1][1], A[1][2], A[1][3], B0[j].z, B0[j].w);
                mma16816(D[j][0], D[j][1], D[j][2], D[j][3],
                         A[2][0], A[2][1], A[2][2], A[2][3], B1[j].x, B1[j].y);
                mma16816(D[j][0], D[j][1], D[j][2], D[j][3],
                         A[3][0], A[3][1], A[3][2], A[3][3], B1[j].z, B1[j].w);
            }
#pragma unroll
            for (int j = 0; j < 4; ++j) {
                mlo = fminf(mlo, fminf(D[j][0], D[j][1]));
                mhi = fminf(mhi, fminf(D[j][2], D[j][3]));
            }
            if (nq & 1) {                   // block boundary (64 codes)
                float rl = mlo, rh = mhi;
                rl = fminf(rl, __shfl_xor_sync(0xffffffffu, rl, 1));
                rl = fminf(rl, __shfl_xor_sync(0xffffffffu, rl, 2));
                rh = fminf(rh, __shfl_xor_sync(0xffffffffu, rh, 1));
                rh = fminf(rh, __shfl_xor_sync(0xffffffffu, rh, 2));
                if (t == 0) {
                    const int blk = tile * 4 + (nq >> 1);
                    g_bmin[(size_t)blk * NPTS + pb + g]     = rl;
                    g_bmin[(size_t)blk * NPTS + pb + g + 8] = rh;
                }
                mlo = INF; mhi = INF;
            }
        }
        __syncthreads();                    // done reading this slot
    }
}

// ---------------------------------------------------------------------------
// K2: flag + exact fp32 refine. One warp per point (8 warps/CTA).
// ---------------------------------------------------------------------------
__global__ __launch_bounds__(256, 2)
void vq_refine(const float* __restrict__ z, const float* __restrict__ emb,
               float* __restrict__ out) {
    __shared__ float zs[8][64];
    const int w    = threadIdx.x >> 5;
    const int lane = threadIdx.x & 31;
    const int p    = blockIdx.x * 8 + w;
    const int b    = p >> 10, pos = p & 1023;

    // stage z row (exact fp32 values)
    zs[w][lane]      = z[(size_t)b * 65536 + (size_t)lane * 1024 + pos];
    zs[w][lane + 32] = z[(size_t)b * 65536 + (size_t)(lane + 32) * 1024 + pos];
    __syncwarp();

    const float a = g_an[p];

    // per-lane 8 blockmins, global min
    float bmv[8];
    float gm = __int_as_float(0x7f800000);
#pragma unroll
    for (int i = 0; i < 8; ++i) {
        bmv[i] = g_bmin[(size_t)(i * 32 + lane) * NPTS + p];
        gm = fminf(gm, bmv[i]);
    }
#pragma unroll
    for (int off = 16; off > 0; off >>= 1)
        gm = fminf(gm, __shfl_xor_sync(0xffffffffu, gm, off));
    const float thr = gm + MARGIN;

    float bd = __int_as_float(0x7f800000);
    int   bk = 0x7fffffff;

#pragma unroll
    for (int i = 0; i < 8; ++i) {
        unsigned m = __ballot_sync(0xffffffffu, bmv[i] < thr);
        while (m) {
            int bit = __ffs(m) - 1;
            m &= m - 1;
            const int blk = i * 32 + bit;
            const int k0 = blk * 64 + 2 * lane;
            const float4* e0 = (const float4*)(emb + (size_t)k0 * DIM);
            const float4* e1 = (const float4*)(emb + (size_t)(k0 + 1) * DIM);
            float c0 = 0.0f, c1 = 0.0f;
#pragma unroll
            for (int q = 0; q < 16; ++q) {
                float4 zz = *(const float4*)&zs[w][q * 4];
                float4 ea = e0[q];
                float4 eb = e1[q];
                c0 = fmaf(zz.x, ea.x, c0); c1 = fmaf(zz.x, eb.x, c1);
                c0 = fmaf(zz.y, ea.y, c0); c1 = fmaf(zz.y, eb.y, c1);
                c0 = fmaf(zz.z, ea.z, c0); c1 = fmaf(zz.z, eb.z, c1);
                c0 = fmaf(zz.w, ea.w, c0); c1 = fmaf(zz.w, eb.w, c1);
            }
            float d0 = fmaf(-2.0f, c0, __fadd_rn(a, g_b[k0]));
            float d1 = fmaf(-2.0f, c1, __fadd_rn(a, g_b[k0 + 1]));
            if (d0 < bd || (d0 == bd && k0 < bk))     { bd = d0; bk = k0;     }
            if (d1 < bd || (d1 == bd && k0 + 1 < bk)) { bd = d1; bk = k0 + 1; }
        }
    }

    // warp argmin with (dist, k) lexicographic tie-break
#pragma unroll
    for (int off = 16; off > 0; off >>= 1) {
        float od = __shfl_xor_sync(0xffffffffu, bd, off);
        int   ok = __shfl_xor_sync(0xffffffffu, bk, off);
        if (od < bd || (od == bd && ok < bk)) { bd = od; bk = ok; }
    }
    if (lane == 0) {
        g_idx[p] = bk;
        out[OFF_IDX + p] = (float)bk;
        out[OFF_USAGE + bk] = 1.0f;
    }
}

// ---------------------------------------------------------------------------
// K3: z_q gather + loss (R4-proven streaming form)
// ---------------------------------------------------------------------------
__global__ void vq_zq_loss(const float* __restrict__ z,
                           const float* __restrict__ emb,
                           float* __restrict__ out) {
    __shared__ double sd[256];
    double acc = 0.0;
    for (int g = blockIdx.x * 256 + threadIdx.x; g < 524288; g += 65536) {
        int d   = (g >> 10) & 63;
        int bb  = g >> 16;
        int pos = g & 1023;
        int k   = g_idx[bb * 1024 + pos];
        float e  = emb[(size_t)k * DIM + d];
        float zv = z[g];
        out[OFF_ZQ + g] = e;
        float diff = e - zv;
        acc += (double)diff * (double)diff;
    }
    sd[threadIdx.x] = acc;
    __syncthreads();
    for (int s = 128; s > 0; s >>= 1) {
        if (threadIdx.x < s) sd[threadIdx.x] += sd[threadIdx.x + s];
        __syncthreads();
    }
    if (threadIdx.x == 0) atomicAdd(&g_loss, sd[0]);
}

// ---------------------------------------------------------------------------
// K4: finalize
// ---------------------------------------------------------------------------
__global__ void vq_finalize(float* out) {
    __shared__ float sf[512];
    float s = 0.0f;
    for (int t = threadIdx.x; t < NCODES; t += 512) s += out[OFF_USAGE + t];
    sf[threadIdx.x] = s;
    __syncthreads();
    for (int st = 256; st > 0; st >>= 1) {
        if (threadIdx.x < st) sf[threadIdx.x] += sf[threadIdx.x + st];
        __syncthreads();
    }
    if (threadIdx.x == 0) {
        float total = sf[0];
        out[OFF_NUNIQ] = total;
        out[OFF_TOTAL] = total / (float)NCODES;
        float m = (float)(g_loss / 524288.0);
        out[OFF_LOSS] = m + 0.25f * m;
    }
}

// ---------------------------------------------------------------------------
extern "C" void kernel_launch(void* const* d_in, const int* in_sizes, int n_in,
                              void* d_out, int out_size) {
    const float* z;
    const float* emb;
    if (in_sizes[0] == 524288) {
        z = (const float*)d_in[0];
        emb = (const float*)d_in[1];
    } else {
        z = (const float*)d_in[1];
        emb = (const float*)d_in[0];
    }
    float* out = (float*)d_out;

    static int attr_set = 0;
    if (!attr_set) {
        cudaFuncSetAttribute(vq_hmma, cudaFuncAttributeMaxDynamicSharedMemorySize, SMK1);
        attr_set = 1;
    }

    vq_prep_z<<<NPTS / 128, 128>>>(z);
    vq_prep_e<<<NCODES / 128, 128>>>(emb, out);
    vq_hmma<<<NPTS / 64, 128, SMK1>>>();
    vq_refine<<<NPTS / 8, 256>>>(z, emb, out);
    vq_zq_loss<<<256, 256>>>(z, emb, out);
    vq_finalize<<<1, 512>>>(out);
}

// round 11
// speedup vs baseline: 2.5152x; 1.0734x over previous
#include <cuda_runtime.h>
#include <cuda_fp16.h>
#include <cstdint>

#define NPTS     8192
#define NCODES   16384
#define DIM      64
#define NBLK     256          // blocks of 64 codes
#define MARGIN   1.0f         // key-unit margin (error budget ~0.15)

// output layout (floats)
#define OFF_ZQ     0
#define OFF_LOSS   524288
#define OFF_IDX    524289
#define OFF_NUNIQ  532481
#define OFF_USAGE  532482
#define OFF_TOTAL  548866

__device__ int    g_idx[NPTS];
__device__ float  g_b[NCODES];
__device__ float  g_an[NPTS];
__device__ __half g_zh[NPTS * DIM];              // permuted fp16 z rows
__device__ __half g_eh[NCODES * DIM];            // permuted fp16 (-16384*e) rows
__device__ float  g_bmin[(size_t)NPTS * NBLK];   // 8 MB blockmins [point][block]
__device__ double g_loss;

// ---------------------------------------------------------------------------
// helpers
// ---------------------------------------------------------------------------
__device__ __forceinline__ unsigned smem_u32(const void* p) {
    unsigned a;
    asm("{ .reg .u64 t; cvta.to.shared.u64 t, %1; cvt.u32.u64 %0, t; }"
        : "=r"(a) : "l"(p));
    return a;
}
__device__ __forceinline__ void cp_async16(unsigned dst, const void* src) {
    asm volatile("cp.async.cg.shared.global [%0], [%1], 16;" :: "r"(dst), "l"(src));
}
#define CP_COMMIT() asm volatile("cp.async.commit_group;")
#define CP_WAIT1()  asm volatile("cp.async.wait_group 1;")

__device__ __forceinline__ void mma16816(float& d0, float& d1, float& d2, float& d3,
                                         unsigned a0, unsigned a1, unsigned a2, unsigned a3,
                                         unsigned b0, unsigned b1) {
    asm("mma.sync.aligned.m16n8k16.row.col.f32.f16.f16.f32 "
        "{%0,%1,%2,%3},{%4,%5,%6,%7},{%8,%9},{%0,%1,%2,%3};"
        : "+f"(d0), "+f"(d1), "+f"(d2), "+f"(d3)
        : "r"(a0), "r"(a1), "r"(a2), "r"(a3), "r"(b0), "r"(b1));
}

// fragment permutation: half index h (0..63) -> dim d
__device__ __forceinline__ int perm_d(int h) {
    int t = h >> 4, s = (h >> 2) & 3, j = h & 3;
    return 16 * s + 2 * t + (j < 2 ? j : 6 + j);
}

// ---------------------------------------------------------------------------
// P1: fused prep — e rows (all 128 blocks) + z rows (blocks < 64)
// ---------------------------------------------------------------------------
__global__ void vq_prep(const float* __restrict__ z, const float* __restrict__ emb,
                        float* __restrict__ out) {
    const int tid = threadIdx.x;
    // e part: k = bid*128 + tid
    {
        int k = blockIdx.x * 128 + tid;
        const float* row = emb + (size_t)k * DIM;
        float ev[64];
        float s = 0.0f;
#pragma unroll 8
        for (int d = 0; d < DIM; ++d) {
            float e = row[d];
            ev[d] = e;
            s = fmaf(e, e, s);
        }
        g_b[k] = s;
        __half arr[64];
#pragma unroll
        for (int h = 0; h < 64; ++h)
            arr[h] = __float2half(ev[perm_d(h)] * -16384.0f);
        uint4* dst = (uint4*)(g_eh + (size_t)k * 64);
#pragma unroll
        for (int i = 0; i < 8; ++i) dst[i] = ((uint4*)arr)[i];
        out[OFF_USAGE + k] = 0.0f;
        if (k == 0) g_loss = 0.0;
    }
    // z part: blocks 0..63
    if (blockIdx.x < 64) {
        int p = blockIdx.x * 128 + tid;
        int b = p >> 10, pos = p & 1023;
        const float* zc = z + (size_t)b * 65536 + pos;
        float s = 0.0f;
        for (int d = 0; d < DIM; ++d) {
            float v = zc[(size_t)d * 1024];
            s = __fadd_rn(s, __fmul_rn(v, v));
        }
        g_an[p] = s;
        __half arr[64];
#pragma unroll
        for (int h = 0; h < 64; ++h)
            arr[h] = __float2half(zc[(size_t)perm_d(h) * 1024]);
        uint4* dst = (uint4*)(g_zh + (size_t)p * 64);
#pragma unroll
        for (int i = 0; i < 8; ++i) dst[i] = ((uint4*)arr)[i];
    }
}

// ---------------------------------------------------------------------------
// K1: HMMA prune — 128 CTAs x 256 thr (8 warps, 2/SMSP).
//     Warps 0-3: points (w&3)*16, tiles 0..63  (codes 0..8191,  ring 0).
//     Warps 4-7: same points,     tiles 64..127 (codes 8192..16383, ring 1).
//     Tiles: 128 codes x 144B padded rows, 3-slot rings.
//     Output: g_bmin[point][block] f32 (block = 64 codes), all 256 blocks.
// ---------------------------------------------------------------------------
#define TCO     128                      // codes per tile
#define NTILE   64                       // tiles per half
#define ROWB    144
#define SLOTB   (TCO * ROWB)             // 18432
#define RINGB   (3 * SLOTB)              // 55296
#define SMK1    (2 * RINGB)              // 110592

__device__ __forceinline__ void k1_load_tile(unsigned sb, int tileG, int htid) {
    const char* src = (const char*)g_eh + (size_t)tileG * TCO * 128;
#pragma unroll
    for (int i = 0; i < 8; ++i) {
        int u = htid + i * 128;          // 1024 granules
        int r = u >> 3, gr = u & 7;
        cp_async16(sb + r * ROWB + gr * 16, src + r * 128 + gr * 16);
    }
}

__global__ __launch_bounds__(256, 1)
void vq_hmma() {
    extern __shared__ char smem[];
    const unsigned sbase = smem_u32(smem);
    const int tid  = threadIdx.x;
    const int half = tid >> 7;           // 0/1: which ring this thread feeds
    const int htid = tid & 127;
    const int w    = tid >> 5;
    const int lane = tid & 31;
    const int g    = lane >> 2;
    const int t    = lane & 3;
    const int pb   = blockIdx.x * 64 + (w & 3) * 16;   // warp's 16 points
    const int tb   = (w >> 2) * NTILE;                 // warp's tile stream base

    const unsigned ring = sbase + half * RINGB;

    // prologue: this half's first two tiles
    k1_load_tile(ring + 0 * SLOTB, half * NTILE + 0, htid); CP_COMMIT();
    k1_load_tile(ring + 1 * SLOTB, half * NTILE + 1, htid); CP_COMMIT();

    // A fragments (persist whole kernel)
    const uint4* za = (const uint4*)(g_zh + (size_t)(pb + g) * 64);
    const uint4* zb = (const uint4*)(g_zh + (size_t)(pb + g + 8) * 64);
    const uint4 rg0 = za[2 * t], rg1 = za[2 * t + 1];
    const uint4 rh0 = zb[2 * t], rh1 = zb[2 * t + 1];
    unsigned A[4][4] = {
        { rg0.x, rh0.x, rg0.y, rh0.y },
        { rg0.z, rh0.z, rg0.w, rh0.w },
        { rg1.x, rh1.x, rg1.y, rh1.y },
        { rg1.z, rh1.z, rg1.w, rh1.w } };

    const float INF = __int_as_float(0x7f800000);
    float mlo = INF, mhi = INF;

    const unsigned myring = sbase + (w >> 2) * RINGB;

    for (int tt = 0; tt < NTILE; ++tt) {
        CP_WAIT1();
        __syncthreads();                 // tile tt of both rings resident
        if (tt + 2 < NTILE) k1_load_tile(ring + ((tt + 2) % 3) * SLOTB,
                                         half * NTILE + tt + 2, htid);
        CP_COMMIT();

        const unsigned bs = myring + (tt % 3) * SLOTB;

#pragma unroll 2
        for (int nq = 0; nq < 4; ++nq) {    // 4 n8-tiles per group (32 codes)
            uint4 B0[4], B1[4];
#pragma unroll
            for (int j = 0; j < 4; ++j) {
                unsigned addr = bs + ((nq * 4 + j) * 8 + g) * ROWB + t * 32;
                asm("ld.shared.v4.u32 {%0,%1,%2,%3}, [%4];"
                    : "=r"(B0[j].x), "=r"(B0[j].y), "=r"(B0[j].z), "=r"(B0[j].w)
                    : "r"(addr));
                asm("ld.shared.v4.u32 {%0,%1,%2,%3}, [%4];"
                    : "=r"(B1[j].x), "=r"(B1[j].y), "=r"(B1[j].z), "=r"(B1[j].w)
                    : "r"(addr + 16));
            }
            float D[4][4];
#pragma unroll
            for (int j = 0; j < 4; ++j)
                D[j][0] = D[j][1] = D[j][2] = D[j][3] = 0.0f;
#pragma unroll
            for (int j = 0; j < 4; ++j) {
                mma16816(D[j][0], D[j][1], D[j][2], D[j][3],
                         A[0][0], A[0][1], A[0][2], A[0][3], B0[j].x, B0[j].y);
                mma16816(D[j][0], D[j][1], D[j][2], D[j][3],
                         A[1][0], A[1][1], A[1][2], A[1][3], B0[j].z, B0[j].w);
                mma16816(D[j][0], D[j][1], D[j][2], D[j][3],
                         A[2][0], A[2][1], A[2][2], A[2][3], B1[j].x, B1[j].y);
                mma16816(D[j][0], D[j][1], D[j][2], D[j][3],
                         A[3][0], A[3][1], A[3][2], A[3][3], B1[j].z, B1[j].w);
            }
#pragma unroll
            for (int j = 0; j < 4; ++j) {
                mlo = fminf(mlo, fminf(D[j][0], D[j][1]));
                mhi = fminf(mhi, fminf(D[j][2], D[j][3]));
            }
            if (nq & 1) {                   // block boundary (64 codes)
                float rl = mlo, rh = mhi;
                rl = fminf(rl, __shfl_xor_sync(0xffffffffu, rl, 1));
                rl = fminf(rl, __shfl_xor_sync(0xffffffffu, rl, 2));
                rh = fminf(rh, __shfl_xor_sync(0xffffffffu, rh, 1));
                rh = fminf(rh, __shfl_xor_sync(0xffffffffu, rh, 2));
                if (t == 0) {
                    const int blk = (tb + tt) * 2 + (nq >> 1);   // 0..255
                    g_bmin[(size_t)(pb + g) * NBLK + blk]     = rl;
                    g_bmin[(size_t)(pb + g + 8) * NBLK + blk] = rh;
                }
                mlo = INF; mhi = INF;
            }
        }
        __syncthreads();                    // done reading this slot
    }
}

// ---------------------------------------------------------------------------
// K2: flag + exact fp32 refine. One warp per point; coalesced blockmin reads.
// ---------------------------------------------------------------------------
__global__ __launch_bounds__(256, 2)
void vq_refine(const float* __restrict__ z, const float* __restrict__ emb,
               float* __restrict__ out) {
    __shared__ float zs[8][64];
    const int w    = threadIdx.x >> 5;
    const int lane = threadIdx.x & 31;
    const int p    = blockIdx.x * 8 + w;
    const int b    = p >> 10, pos = p & 1023;

    // stage z row (exact fp32 values)
    zs[w][lane]      = z[(size_t)b * 65536 + (size_t)lane * 1024 + pos];
    zs[w][lane + 32] = z[(size_t)b * 65536 + (size_t)(lane + 32) * 1024 + pos];
    __syncwarp();

    const float a = g_an[p];

    // per-lane 8 blockmins (coalesced: [point][block]), global min
    float bmv[8];
    float gm = __int_as_float(0x7f800000);
#pragma unroll
    for (int i = 0; i < 8; ++i) {
        bmv[i] = g_bmin[(size_t)p * NBLK + i * 32 + lane];
        gm = fminf(gm, bmv[i]);
    }
#pragma unroll
    for (int off = 16; off > 0; off >>= 1)
        gm = fminf(gm, __shfl_xor_sync(0xffffffffu, gm, off));
    const float thr = gm + MARGIN;

    float bd = __int_as_float(0x7f800000);
    int   bk = 0x7fffffff;

#pragma unroll
    for (int i = 0; i < 8; ++i) {
        unsigned m = __ballot_sync(0xffffffffu, bmv[i] < thr);
        while (m) {
            int bit = __ffs(m) - 1;
            m &= m - 1;
            const int blk = i * 32 + bit;
            const int k0 = blk * 64 + 2 * lane;
            const float4* e0 = (const float4*)(emb + (size_t)k0 * DIM);
            const float4* e1 = (const float4*)(emb + (size_t)(k0 + 1) * DIM);
            float c0 = 0.0f, c1 = 0.0f;
#pragma unroll
            for (int q = 0; q < 16; ++q) {
                float4 zz = *(const float4*)&zs[w][q * 4];
                float4 ea = e0[q];
                float4 eb = e1[q];
                c0 = fmaf(zz.x, ea.x, c0); c1 = fmaf(zz.x, eb.x, c1);
                c0 = fmaf(zz.y, ea.y, c0); c1 = fmaf(zz.y, eb.y, c1);
                c0 = fmaf(zz.z, ea.z, c0); c1 = fmaf(zz.z, eb.z, c1);
                c0 = fmaf(zz.w, ea.w, c0); c1 = fmaf(zz.w, eb.w, c1);
            }
            float d0 = fmaf(-2.0f, c0, __fadd_rn(a, g_b[k0]));
            float d1 = fmaf(-2.0f, c1, __fadd_rn(a, g_b[k0 + 1]));
            if (d0 < bd || (d0 == bd && k0 < bk))     { bd = d0; bk = k0;     }
            if (d1 < bd || (d1 == bd && k0 + 1 < bk)) { bd = d1; bk = k0 + 1; }
        }
    }

    // warp argmin with (dist, k) lexicographic tie-break
#pragma unroll
    for (int off = 16; off > 0; off >>= 1) {
        float od = __shfl_xor_sync(0xffffffffu, bd, off);
        int   ok = __shfl_xor_sync(0xffffffffu, bk, off);
        if (od < bd || (od == bd && ok < bk)) { bd = od; bk = ok; }
    }
    if (lane == 0) {
        g_idx[p] = bk;
        out[OFF_IDX + p] = (float)bk;
        out[OFF_USAGE + bk] = 1.0f;
    }
}

// ---------------------------------------------------------------------------
// K3: z_q gather + loss
// ---------------------------------------------------------------------------
__global__ void vq_zq_loss(const float* __restrict__ z,
                           const float* __restrict__ emb,
                           float* __restrict__ out) {
    __shared__ double sd[256];
    double acc = 0.0;
    for (int g = blockIdx.x * 256 + threadIdx.x; g < 524288; g += 65536) {
        int d   = (g >> 10) & 63;
        int bb  = g >> 16;
        int pos = g & 1023;
        int k   = g_idx[bb * 1024 + pos];
        float e  = emb[(size_t)k * DIM + d];
        float zv = z[g];
        out[OFF_ZQ + g] = e;
        float diff = e - zv;
        acc += (double)diff * (double)diff;
    }
    sd[threadIdx.x] = acc;
    __syncthreads();
    for (int s = 128; s > 0; s >>= 1) {
        if (threadIdx.x < s) sd[threadIdx.x] += sd[threadIdx.x + s];
        __syncthreads();
    }
    if (threadIdx.x == 0) atomicAdd(&g_loss, sd[0]);
}

// ---------------------------------------------------------------------------
// K4: finalize
// ---------------------------------------------------------------------------
__global__ void vq_finalize(float* out) {
    __shared__ float sf[512];
    float s = 0.0f;
    for (int t = threadIdx.x; t < NCODES; t += 512) s += out[OFF_USAGE + t];
    sf[threadIdx.x] = s;
    __syncthreads();
    for (int st = 256; st > 0; st >>= 1) {
        if (threadIdx.x < st) sf[threadIdx.x] += sf[threadIdx.x + st];
        __syncthreads();
    }
    if (threadIdx.x == 0) {
        float total = sf[0];
        out[OFF_NUNIQ] = total;
        out[OFF_TOTAL] = total / (float)NCODES;
        float m = (float)(g_loss / 524288.0);
        out[OFF_LOSS] = m + 0.25f * m;
    }
}

// ---------------------------------------------------------------------------
extern "C" void kernel_launch(void* const* d_in, const int* in_sizes, int n_in,
                              void* d_out, int out_size) {
    const float* z;
    const float* emb;
    if (in_sizes[0] == 524288) {
        z = (const float*)d_in[0];
        emb = (const float*)d_in[1];
    } else {
        z = (const float*)d_in[1];
        emb = (const float*)d_in[0];
    }
    float* out = (float*)d_out;

    static int attr_set = 0;
    if (!attr_set) {
        cudaFuncSetAttribute(vq_hmma, cudaFuncAttributeMaxDynamicSharedMemorySize, SMK1);
        attr_set = 1;
    }

    vq_prep<<<NCODES / 128, 128>>>(z, emb, out);
    vq_hmma<<<NPTS / 64, 256, SMK1>>>();
    vq_refine<<<NPTS / 8, 256>>>(z, emb, out);
    vq_zq_loss<<<256, 256>>>(z, emb, out);
    vq_finalize<<<1, 512>>>(out);
}

// round 12
// speedup vs baseline: 2.7196x; 1.0812x over previous
#include <cuda_runtime.h>
#include <cuda_fp16.h>
#include <cstdint>

#define NPTS     8192
#define NCODES   16384
#define DIM      64
#define NBLK     256          // blocks of 64 codes
#define MARGIN   1.0f         // key-unit margin (error budget ~0.15)

// output layout (floats)
#define OFF_ZQ     0
#define OFF_LOSS   524288
#define OFF_IDX    524289
#define OFF_NUNIQ  532481
#define OFF_USAGE  532482
#define OFF_TOTAL  548866

__device__ int    g_idx[NPTS];
__device__ float  g_b[NCODES];
__device__ float  g_an[NPTS];
__device__ __half g_zh[NPTS * DIM];              // permuted fp16 z rows
__device__ __half g_eh[NCODES * DIM];            // permuted fp16 (-16384*e) rows
__device__ float  g_bmin[(size_t)NPTS * NBLK];   // 8 MB blockmins [point][block]
__device__ double g_lp[256];                     // per-block loss partials
__device__ int    g_done;
__device__ int    g_uniq;

// ---------------------------------------------------------------------------
// helpers
// ---------------------------------------------------------------------------
__device__ __forceinline__ unsigned smem_u32(const void* p) {
    unsigned a;
    asm("{ .reg .u64 t; cvta.to.shared.u64 t, %1; cvt.u32.u64 %0, t; }"
        : "=r"(a) : "l"(p));
    return a;
}
__device__ __forceinline__ void cp_async16(unsigned dst, const void* src) {
    asm volatile("cp.async.cg.shared.global [%0], [%1], 16;" :: "r"(dst), "l"(src));
}
#define CP_COMMIT() asm volatile("cp.async.commit_group;")
#define CP_WAIT1()  asm volatile("cp.async.wait_group 1;")
#define HBAR(id)    asm volatile("bar.sync %0, 128;" :: "r"(id) : "memory")

__device__ __forceinline__ void mma16816(float& d0, float& d1, float& d2, float& d3,
                                         unsigned a0, unsigned a1, unsigned a2, unsigned a3,
                                         unsigned b0, unsigned b1) {
    asm("mma.sync.aligned.m16n8k16.row.col.f32.f16.f16.f32 "
        "{%0,%1,%2,%3},{%4,%5,%6,%7},{%8,%9},{%0,%1,%2,%3};"
        : "+f"(d0), "+f"(d1), "+f"(d2), "+f"(d3)
        : "r"(a0), "r"(a1), "r"(a2), "r"(a3), "r"(b0), "r"(b1));
}

// fragment permutation: half index h (0..63) -> dim d
__device__ __forceinline__ int perm_d(int h) {
    int t = h >> 4, s = (h >> 2) & 3, j = h & 3;
    return 16 * s + 2 * t + (j < 2 ? j : 6 + j);
}

// ---------------------------------------------------------------------------
// P1: fused prep — e rows (all 128 blocks) + z rows (blocks < 64)
// ---------------------------------------------------------------------------
__global__ void vq_prep(const float* __restrict__ z, const float* __restrict__ emb,
                        float* __restrict__ out) {
    const int tid = threadIdx.x;
    // e part: k = bid*128 + tid
    {
        int k = blockIdx.x * 128 + tid;
        const float4* row = (const float4*)(emb + (size_t)k * DIM);
        float ev[64];
        float s = 0.0f;
#pragma unroll
        for (int q = 0; q < 16; ++q) {
            float4 v = row[q];
            ev[q * 4]     = v.x; ev[q * 4 + 1] = v.y;
            ev[q * 4 + 2] = v.z; ev[q * 4 + 3] = v.w;
            s = fmaf(v.x, v.x, s); s = fmaf(v.y, v.y, s);
            s = fmaf(v.z, v.z, s); s = fmaf(v.w, v.w, s);
        }
        g_b[k] = s;
        __half arr[64];
#pragma unroll
        for (int h = 0; h < 64; ++h)
            arr[h] = __float2half(ev[perm_d(h)] * -16384.0f);
        uint4* dst = (uint4*)(g_eh + (size_t)k * 64);
#pragma unroll
        for (int i = 0; i < 8; ++i) dst[i] = ((uint4*)arr)[i];
        out[OFF_USAGE + k] = 0.0f;
        if (k == 0) { g_done = 0; g_uniq = 0; }
    }
    // z part: blocks 0..63
    if (blockIdx.x < 64) {
        int p = blockIdx.x * 128 + tid;
        int b = p >> 10, pos = p & 1023;
        const float* zc = z + (size_t)b * 65536 + pos;
        float s = 0.0f;
        for (int d = 0; d < DIM; ++d) {
            float v = zc[(size_t)d * 1024];
            s = __fadd_rn(s, __fmul_rn(v, v));
        }
        g_an[p] = s;
        __half arr[64];
#pragma unroll
        for (int h = 0; h < 64; ++h)
            arr[h] = __float2half(zc[(size_t)perm_d(h) * 1024]);
        uint4* dst = (uint4*)(g_zh + (size_t)p * 64);
#pragma unroll
        for (int i = 0; i < 8; ++i) dst[i] = ((uint4*)arr)[i];
    }
}

// ---------------------------------------------------------------------------
// K1: HMMA prune — 128 CTAs x 256 thr (8 warps, 2/SMSP).
//     Warps 0-3: points (w&3)*16, tiles 0..63   (codes 0..8191,   ring 0).
//     Warps 4-7: same points,     tiles 64..127 (codes 8192..16383, ring 1).
//     Per-half named barriers decouple the two rings.
//     Output: g_bmin[point][block] f32 (block = 64 codes), all 256 blocks.
// ---------------------------------------------------------------------------
#define TCO     128                      // codes per tile
#define NTILE   64                       // tiles per half
#define ROWB    144
#define SLOTB   (TCO * ROWB)             // 18432
#define RINGB   (3 * SLOTB)              // 55296
#define SMK1    (2 * RINGB)              // 110592

__device__ __forceinline__ void k1_load_tile(unsigned sb, int tileG, int htid) {
    const char* src = (const char*)g_eh + (size_t)tileG * TCO * 128;
#pragma unroll
    for (int i = 0; i < 8; ++i) {
        int u = htid + i * 128;          // 1024 granules
        int r = u >> 3, gr = u & 7;
        cp_async16(sb + r * ROWB + gr * 16, src + r * 128 + gr * 16);
    }
}

__global__ __launch_bounds__(256, 1)
void vq_hmma() {
    extern __shared__ char smem[];
    const unsigned sbase = smem_u32(smem);
    const int tid  = threadIdx.x;
    const int half = tid >> 7;           // 0/1: ring this thread feeds+consumes
    const int htid = tid & 127;
    const int w    = tid >> 5;
    const int lane = tid & 31;
    const int g    = lane >> 2;
    const int t    = lane & 3;
    const int pb   = blockIdx.x * 64 + (w & 3) * 16;   // warp's 16 points
    const int tb   = half * NTILE;                     // warp's tile stream base

    const unsigned ring = sbase + half * RINGB;

    // prologue: this half's first two tiles
    k1_load_tile(ring + 0 * SLOTB, half * NTILE + 0, htid); CP_COMMIT();
    k1_load_tile(ring + 1 * SLOTB, half * NTILE + 1, htid); CP_COMMIT();

    // A fragments (persist whole kernel)
    const uint4* za = (const uint4*)(g_zh + (size_t)(pb + g) * 64);
    const uint4* zb = (const uint4*)(g_zh + (size_t)(pb + g + 8) * 64);
    const uint4 rg0 = za[2 * t], rg1 = za[2 * t + 1];
    const uint4 rh0 = zb[2 * t], rh1 = zb[2 * t + 1];
    unsigned A[4][4] = {
        { rg0.x, rh0.x, rg0.y, rh0.y },
        { rg0.z, rh0.z, rg0.w, rh0.w },
        { rg1.x, rh1.x, rg1.y, rh1.y },
        { rg1.z, rh1.z, rg1.w, rh1.w } };

    const float INF = __int_as_float(0x7f800000);
    float mlo = INF, mhi = INF;

    for (int tt = 0; tt < NTILE; ++tt) {
        CP_WAIT1();
        HBAR(1 + half);                  // tile tt of MY ring resident
        if (tt + 2 < NTILE) k1_load_tile(ring + ((tt + 2) % 3) * SLOTB,
                                         half * NTILE + tt + 2, htid);
        CP_COMMIT();

        const unsigned bs = ring + (tt % 3) * SLOTB;

#pragma unroll 2
        for (int nq = 0; nq < 4; ++nq) {    // 4 n8-tiles per group (32 codes)
            uint4 B0[4], B1[4];
#pragma unroll
            for (int j = 0; j < 4; ++j) {
                unsigned addr = bs + ((nq * 4 + j) * 8 + g) * ROWB + t * 32;
                asm("ld.shared.v4.u32 {%0,%1,%2,%3}, [%4];"
                    : "=r"(B0[j].x), "=r"(B0[j].y), "=r"(B0[j].z), "=r"(B0[j].w)
                    : "r"(addr));
                asm("ld.shared.v4.u32 {%0,%1,%2,%3}, [%4];"
                    : "=r"(B1[j].x), "=r"(B1[j].y), "=r"(B1[j].z), "=r"(B1[j].w)
                    : "r"(addr + 16));
            }
            float D[4][4];
#pragma unroll
            for (int j = 0; j < 4; ++j)
                D[j][0] = D[j][1] = D[j][2] = D[j][3] = 0.0f;
#pragma unroll
            for (int j = 0; j < 4; ++j) {
                mma16816(D[j][0], D[j][1], D[j][2], D[j][3],
                         A[0][0], A[0][1], A[0][2], A[0][3], B0[j].x, B0[j].y);
                mma16816(D[j][0], D[j][1], D[j][2], D[j][3],
                         A[1][0], A[1][1], A[1][2], A[1][3], B0[j].z, B0[j].w);
                mma16816(D[j][0], D[j][1], D[j][2], D[j][3],
                         A[2][0], A[2][1], A[2][2], A[2][3], B1[j].x, B1[j].y);
                mma16816(D[j][0], D[j][1], D[j][2], D[j][3],
                         A[3][0], A[3][1], A[3][2], A[3][3], B1[j].z, B1[j].w);
            }
#pragma unroll
            for (int j = 0; j < 4; ++j) {
                mlo = fminf(mlo, fminf(D[j][0], D[j][1]));
                mhi = fminf(mhi, fminf(D[j][2], D[j][3]));
            }
            if (nq & 1) {                   // block boundary (64 codes)
                float rl = mlo, rh = mhi;
                rl = fminf(rl, __shfl_xor_sync(0xffffffffu, rl, 1));
                rl = fminf(rl, __shfl_xor_sync(0xffffffffu, rl, 2));
                rh = fminf(rh, __shfl_xor_sync(0xffffffffu, rh, 1));
                rh = fminf(rh, __shfl_xor_sync(0xffffffffu, rh, 2));
                if (t == 0) {
                    const int blk = (tb + tt) * 2 + (nq >> 1);   // 0..255
                    g_bmin[(size_t)(pb + g) * NBLK + blk]     = rl;
                    g_bmin[(size_t)(pb + g + 8) * NBLK + blk] = rh;
                }
                mlo = INF; mhi = INF;
            }
        }
        HBAR(1 + half);                     // my half done reading this slot
    }
}

// ---------------------------------------------------------------------------
// K2: flag + exact fp32 refine. One warp per point; coalesced blockmin reads.
//     Also counts unique codes via atomicExch transition 0 -> 1.
// ---------------------------------------------------------------------------
__global__ __launch_bounds__(256, 2)
void vq_refine(const float* __restrict__ z, const float* __restrict__ emb,
               float* __restrict__ out) {
    __shared__ float zs[8][64];
    const int w    = threadIdx.x >> 5;
    const int lane = threadIdx.x & 31;
    const int p    = blockIdx.x * 8 + w;
    const int b    = p >> 10, pos = p & 1023;

    // stage z row (exact fp32 values)
    zs[w][lane]      = z[(size_t)b * 65536 + (size_t)lane * 1024 + pos];
    zs[w][lane + 32] = z[(size_t)b * 65536 + (size_t)(lane + 32) * 1024 + pos];
    __syncwarp();

    const float a = g_an[p];

    // per-lane 8 blockmins (coalesced: [point][block]), global min
    float bmv[8];
    float gm = __int_as_float(0x7f800000);
#pragma unroll
    for (int i = 0; i < 8; ++i) {
        bmv[i] = g_bmin[(size_t)p * NBLK + i * 32 + lane];
        gm = fminf(gm, bmv[i]);
    }
#pragma unroll
    for (int off = 16; off > 0; off >>= 1)
        gm = fminf(gm, __shfl_xor_sync(0xffffffffu, gm, off));
    const float thr = gm + MARGIN;

    float bd = __int_as_float(0x7f800000);
    int   bk = 0x7fffffff;

#pragma unroll
    for (int i = 0; i < 8; ++i) {
        unsigned m = __ballot_sync(0xffffffffu, bmv[i] < thr);
        while (m) {
            int bit = __ffs(m) - 1;
            m &= m - 1;
            const int blk = i * 32 + bit;
            const int k0 = blk * 64 + 2 * lane;
            const float4* e0 = (const float4*)(emb + (size_t)k0 * DIM);
            const float4* e1 = (const float4*)(emb + (size_t)(k0 + 1) * DIM);
            float c0 = 0.0f, c1 = 0.0f;
#pragma unroll
            for (int q = 0; q < 16; ++q) {
                float4 zz = *(const float4*)&zs[w][q * 4];
                float4 ea = e0[q];
                float4 eb = e1[q];
                c0 = fmaf(zz.x, ea.x, c0); c1 = fmaf(zz.x, eb.x, c1);
                c0 = fmaf(zz.y, ea.y, c0); c1 = fmaf(zz.y, eb.y, c1);
                c0 = fmaf(zz.z, ea.z, c0); c1 = fmaf(zz.z, eb.z, c1);
                c0 = fmaf(zz.w, ea.w, c0); c1 = fmaf(zz.w, eb.w, c1);
            }
            float d0 = fmaf(-2.0f, c0, __fadd_rn(a, g_b[k0]));
            float d1 = fmaf(-2.0f, c1, __fadd_rn(a, g_b[k0 + 1]));
            if (d0 < bd || (d0 == bd && k0 < bk))     { bd = d0; bk = k0;     }
            if (d1 < bd || (d1 == bd && k0 + 1 < bk)) { bd = d1; bk = k0 + 1; }
        }
    }

    // warp argmin with (dist, k) lexicographic tie-break
#pragma unroll
    for (int off = 16; off > 0; off >>= 1) {
        float od = __shfl_xor_sync(0xffffffffu, bd, off);
        int   ok = __shfl_xor_sync(0xffffffffu, bk, off);
        if (od < bd || (od == bd && ok < bk)) { bd = od; bk = ok; }
    }
    if (lane == 0) {
        g_idx[p] = bk;
        out[OFF_IDX + p] = (float)bk;
        float old = atomicExch(&out[OFF_USAGE + bk], 1.0f);
        if (old == 0.0f) atomicAdd(&g_uniq, 1);
    }
}

// ---------------------------------------------------------------------------
// K3: z_q gather + loss, vectorized; last block writes the scalars.
// ---------------------------------------------------------------------------
__global__ void vq_zq_loss(const float* __restrict__ z,
                           const float* __restrict__ emb,
                           float* __restrict__ out) {
    __shared__ double sd[256];
    __shared__ int lastflag;
    const int tid = threadIdx.x;
    double acc = 0.0;
#pragma unroll
    for (int h = 0; h < 2; ++h) {
        const int g = blockIdx.x * 2048 + h * 1024 + tid * 4;
        const int d   = (g >> 10) & 63;
        const int bb  = g >> 16;
        const int pos = g & 1023;
        const int nb  = bb * 1024 + pos;
        float4 zv = *(const float4*)(z + g);
        int k0 = g_idx[nb],     k1 = g_idx[nb + 1];
        int k2 = g_idx[nb + 2], k3 = g_idx[nb + 3];
        float4 ev;
        ev.x = emb[(size_t)k0 * DIM + d];
        ev.y = emb[(size_t)k1 * DIM + d];
        ev.z = emb[(size_t)k2 * DIM + d];
        ev.w = emb[(size_t)k3 * DIM + d];
        *(float4*)(out + OFF_ZQ + g) = ev;
        float f0 = ev.x - zv.x, f1 = ev.y - zv.y;
        float f2 = ev.z - zv.z, f3 = ev.w - zv.w;
        acc += (double)f0 * f0 + (double)f1 * f1
             + (double)f2 * f2 + (double)f3 * f3;
    }
    sd[tid] = acc;
    __syncthreads();
    for (int s = 128; s > 0; s >>= 1) {
        if (tid < s) sd[tid] += sd[tid + s];
        __syncthreads();
    }
    if (tid == 0) {
        g_lp[blockIdx.x] = sd[0];
        __threadfence();
        lastflag = (atomicAdd(&g_done, 1) == 255);
    }
    __syncthreads();
    if (lastflag) {
        sd[tid] = g_lp[tid];
        __syncthreads();
        for (int s = 128; s > 0; s >>= 1) {
            if (tid < s) sd[tid] += sd[tid + s];
            __syncthreads();
        }
        if (tid == 0) {
            float m = (float)(sd[0] / 524288.0);
            out[OFF_LOSS]  = m + 0.25f * m;
            float total = (float)g_uniq;
            out[OFF_NUNIQ] = total;
            out[OFF_TOTAL] = total / (float)NCODES;
        }
    }
}

// ---------------------------------------------------------------------------
extern "C" void kernel_launch(void* const* d_in, const int* in_sizes, int n_in,
                              void* d_out, int out_size) {
    const float* z;
    const float* emb;
    if (in_sizes[0] == 524288) {
        z = (const float*)d_in[0];
        emb = (const float*)d_in[1];
    } else {
        z = (const float*)d_in[1];
        emb = (const float*)d_in[0];
    }
    float* out = (float*)d_out;

    static int attr_set = 0;
    if (!attr_set) {
        cudaFuncSetAttribute(vq_hmma, cudaFuncAttributeMaxDynamicSharedMemorySize, SMK1);
        attr_set = 1;
    }

    vq_prep<<<NCODES / 128, 128>>>(z, emb, out);
    vq_hmma<<<NPTS / 64, 256, SMK1>>>();
    vq_refine<<<NPTS / 8, 256>>>(z, emb, out);
    vq_zq_loss<<<256, 256>>>(z, emb, out);
}